// round 1
// baseline (speedup 1.0000x reference)
#include <cuda_runtime.h>
#include <math.h>

// Fixed problem shape (registry problem has fixed shapes)
#define NMAX 100000
#define QMAX 256
#define RMAX 401

// Scratch (device globals — no allocation allowed)
__device__ float g_tableS[NMAX * 64];           // Ws·hidden + Ws_b      (25.6 MB)
__device__ float g_tableR[RMAX * 64];           // Wr·rela
__device__ float g_tableQ[QMAX * 64];           // Wq·q_emb
__device__ float g_tableQR[QMAX * RMAX * 64];   // Wqr·(rela⊙q_emb)      (26.3 MB)
__device__ float g_agg[NMAX * 64];              // segment-sum accumulator (25.6 MB)

// -----------------------------------------------------------------------------
// GEMM (NT): out[m,a] = sum_d X[m,d] * W[a,d] (+ bias[a]).  D = A = 64.
// Block tile: 32 rows x 64 cols. 256 threads, each computes a 2x4 register tile.
// -----------------------------------------------------------------------------
#define MAC_ROW(acc, xv)                                                        \
    acc.x = fmaf(xv.x, w0.x, fmaf(xv.y, w1.x, fmaf(xv.z, w2.x, fmaf(xv.w, w3.x, acc.x)))); \
    acc.y = fmaf(xv.x, w0.y, fmaf(xv.y, w1.y, fmaf(xv.z, w2.y, fmaf(xv.w, w3.y, acc.y)))); \
    acc.z = fmaf(xv.x, w0.z, fmaf(xv.y, w1.z, fmaf(xv.z, w2.z, fmaf(xv.w, w3.z, acc.z)))); \
    acc.w = fmaf(xv.x, w0.w, fmaf(xv.y, w1.w, fmaf(xv.z, w2.w, fmaf(xv.w, w3.w, acc.w))));

__global__ void gemm_nt_kernel(const float* __restrict__ X,
                               const float* __restrict__ W,
                               const float* __restrict__ bias,
                               float* __restrict__ out, int M)
{
    __shared__ float Wt[64 * 64];   // Wt[d*64 + a] = W[a*64 + d]
    __shared__ float Xs[32 * 64];
    const int tid = threadIdx.x;

    // Load W transposed into smem (contiguous STS; scattered 4B LDG hits L1/L2)
    #pragma unroll
    for (int i = tid; i < 4096; i += 256)
        Wt[i] = W[((i & 63) << 6) | (i >> 6)];

    const int m0 = blockIdx.x * 32;
    // Load 32 X rows (zero-pad past M)
    #pragma unroll
    for (int i = tid; i < 512; i += 256) {
        int row = i >> 4, c4 = i & 15;
        float4 v = make_float4(0.f, 0.f, 0.f, 0.f);
        if (m0 + row < M) v = ((const float4*)X)[(size_t)(m0 + row) * 16 + c4];
        ((float4*)Xs)[i] = v;
    }
    __syncthreads();

    const int tx = tid & 15, ty = tid >> 4;
    const int a0 = tx * 4, n0 = ty * 2;

    float4 acc0 = bias ? *(const float4*)&bias[a0] : make_float4(0.f, 0.f, 0.f, 0.f);
    float4 acc1 = acc0;

    #pragma unroll
    for (int d = 0; d < 64; d += 4) {
        float4 x0 = *(const float4*)&Xs[n0 * 64 + d];
        float4 x1 = *(const float4*)&Xs[(n0 + 1) * 64 + d];
        float4 w0 = *(const float4*)&Wt[(d + 0) * 64 + a0];
        float4 w1 = *(const float4*)&Wt[(d + 1) * 64 + a0];
        float4 w2 = *(const float4*)&Wt[(d + 2) * 64 + a0];
        float4 w3 = *(const float4*)&Wt[(d + 3) * 64 + a0];
        MAC_ROW(acc0, x0)
        MAC_ROW(acc1, x1)
    }

    if (m0 + n0 < M)     *(float4*)&out[(size_t)(m0 + n0) * 64 + a0]     = acc0;
    if (m0 + n0 + 1 < M) *(float4*)&out[(size_t)(m0 + n0 + 1) * 64 + a0] = acc1;
}

// -----------------------------------------------------------------------------
// Same GEMM, but X rows are formed on the fly: row p=(q,r) -> q_emb[q] ⊙ rela[r]
// -----------------------------------------------------------------------------
__global__ void gemm_qr_kernel(const float* __restrict__ qe,
                               const float* __restrict__ re,
                               const float* __restrict__ W,
                               float* __restrict__ out, int M, int R)
{
    __shared__ float Wt[64 * 64];
    __shared__ float Xs[32 * 64];
    const int tid = threadIdx.x;

    #pragma unroll
    for (int i = tid; i < 4096; i += 256)
        Wt[i] = W[((i & 63) << 6) | (i >> 6)];

    const int m0 = blockIdx.x * 32;
    #pragma unroll
    for (int i = tid; i < 512; i += 256) {
        int row = i >> 4, c4 = i & 15;
        float4 v = make_float4(0.f, 0.f, 0.f, 0.f);
        int p = m0 + row;
        if (p < M) {
            int q = p / R;
            int r = p - q * R;
            float4 a = ((const float4*)qe)[q * 16 + c4];
            float4 b = ((const float4*)re)[r * 16 + c4];
            v = make_float4(a.x * b.x, a.y * b.y, a.z * b.z, a.w * b.w);
        }
        ((float4*)Xs)[i] = v;
    }
    __syncthreads();

    const int tx = tid & 15, ty = tid >> 4;
    const int a0 = tx * 4, n0 = ty * 2;
    float4 acc0 = make_float4(0.f, 0.f, 0.f, 0.f);
    float4 acc1 = acc0;

    #pragma unroll
    for (int d = 0; d < 64; d += 4) {
        float4 x0 = *(const float4*)&Xs[n0 * 64 + d];
        float4 x1 = *(const float4*)&Xs[(n0 + 1) * 64 + d];
        float4 w0 = *(const float4*)&Wt[(d + 0) * 64 + a0];
        float4 w1 = *(const float4*)&Wt[(d + 1) * 64 + a0];
        float4 w2 = *(const float4*)&Wt[(d + 2) * 64 + a0];
        float4 w3 = *(const float4*)&Wt[(d + 3) * 64 + a0];
        MAC_ROW(acc0, x0)
        MAC_ROW(acc1, x1)
    }

    if (m0 + n0 < M)     *(float4*)&out[(size_t)(m0 + n0) * 64 + a0]     = acc0;
    if (m0 + n0 + 1 < M) *(float4*)&out[(size_t)(m0 + n0 + 1) * 64 + a0] = acc1;
}

// -----------------------------------------------------------------------------
// Zero the aggregation buffer
// -----------------------------------------------------------------------------
__global__ void zero_kernel(float4* __restrict__ p, int n4)
{
    int i = blockIdx.x * blockDim.x + threadIdx.x;
    if (i < n4) p[i] = make_float4(0.f, 0.f, 0.f, 0.f);
}

// -----------------------------------------------------------------------------
// Edge kernel: one warp per edge. Gather 4 precomputed 64-vectors, fuse,
// relu, dot with wa (warp reduce), sigmoid -> alpha; message = alpha*hs*hr,
// vector-atomic scatter into g_agg[obj].
// -----------------------------------------------------------------------------
__global__ void edge_kernel(const int* __restrict__ edges,
                            const float* __restrict__ hidden,
                            const float* __restrict__ rela,
                            const float* __restrict__ wa_W,
                            const float* __restrict__ wa_b,
                            const float* __restrict__ tS,
                            const float* __restrict__ tR,
                            const float* __restrict__ tQ,
                            const float* __restrict__ tQR,
                            float* __restrict__ agg,
                            float* __restrict__ alpha_out,
                            int E, int R)
{
    const int gw   = (blockIdx.x * blockDim.x + threadIdx.x) >> 5;
    const int lane = threadIdx.x & 31;
    if (gw >= E) return;

    const int* er = edges + (size_t)gw * 6;
    const int q = __ldg(er + 0);
    const int r = __ldg(er + 2);
    const int s = __ldg(er + 4);
    const int o = __ldg(er + 5);

    const int c = lane * 2;
    float2 ps  = *(const float2*)&tS[(size_t)s * 64 + c];
    float2 pr  = *(const float2*)&tR[(size_t)r * 64 + c];
    float2 pq  = *(const float2*)&tQ[(size_t)q * 64 + c];
    float2 pqr = *(const float2*)&tQR[((size_t)q * R + r) * 64 + c];

    float px = fmaxf(ps.x + pr.x + pq.x + pqr.x, 0.f);
    float py = fmaxf(ps.y + pr.y + pq.y + pqr.y, 0.f);

    float2 wa = *(const float2*)&wa_W[c];
    float part = px * wa.x + py * wa.y;
    #pragma unroll
    for (int off = 16; off; off >>= 1)
        part += __shfl_xor_sync(0xffffffffu, part, off);

    float alpha = 1.0f / (1.0f + expf(-(part + wa_b[0])));
    if (lane == 0) alpha_out[gw] = alpha;

    float2 hs = *(const float2*)&hidden[(size_t)s * 64 + c];
    float2 hr = *(const float2*)&rela[(size_t)r * 64 + c];
    float mx = alpha * hs.x * hr.x;
    float my = alpha * hs.y * hr.y;

    float* dst = &agg[(size_t)o * 64 + c];
    asm volatile("red.global.add.v2.f32 [%0], {%1, %2};"
                 :: "l"(dst), "f"(mx), "f"(my) : "memory");
}

// -----------------------------------------------------------------------------
// Launch
// inputs: 0 q_sub(int,Q) 1 q_emb(Q*64) 2 rela_embed(R*64) 3 hidden(N*64)
//         4 edges(E*6 int) 5 n_nodes 6 Ws_W 7 Ws_b 8 Wr_W 9 Wq_W 10 Wqr_W
//         11 wa_W(64) 12 wa_b(1) 13 Wh_W(64*64)
// output: hidden_new (N*64) followed by alpha (E)
// -----------------------------------------------------------------------------
extern "C" void kernel_launch(void* const* d_in, const int* in_sizes, int n_in,
                              void* d_out, int out_size)
{
    const float* q_emb  = (const float*)d_in[1];
    const float* rela   = (const float*)d_in[2];
    const float* hidden = (const float*)d_in[3];
    const int*   edges  = (const int*)d_in[4];
    const float* Ws_W   = (const float*)d_in[6];
    const float* Ws_b   = (const float*)d_in[7];
    const float* Wr_W   = (const float*)d_in[8];
    const float* Wq_W   = (const float*)d_in[9];
    const float* Wqr_W  = (const float*)d_in[10];
    const float* wa_W   = (const float*)d_in[11];
    const float* wa_b   = (const float*)d_in[12];
    const float* Wh_W   = (const float*)d_in[13];

    const int Q = in_sizes[0];
    const int R = in_sizes[2] / 64;
    const int N = in_sizes[3] / 64;
    const int E = in_sizes[4] / 6;

    float* out = (float*)d_out;
    float* alpha_out = out + (size_t)N * 64;

    float *tS, *tR, *tQ, *tQR, *agg;
    cudaGetSymbolAddress((void**)&tS,  g_tableS);
    cudaGetSymbolAddress((void**)&tR,  g_tableR);
    cudaGetSymbolAddress((void**)&tQ,  g_tableQ);
    cudaGetSymbolAddress((void**)&tQR, g_tableQR);
    cudaGetSymbolAddress((void**)&agg, g_agg);

    // Precompute tables
    gemm_nt_kernel<<<(N + 31) / 32, 256>>>(hidden, Ws_W, Ws_b, tS, N);
    gemm_nt_kernel<<<(R + 31) / 32, 256>>>(rela,   Wr_W, nullptr, tR, R);
    gemm_nt_kernel<<<(Q + 31) / 32, 256>>>(q_emb,  Wq_W, nullptr, tQ, Q);
    gemm_qr_kernel<<<(Q * R + 31) / 32, 256>>>(q_emb, rela, Wqr_W, tQR, Q * R, R);

    // Zero accumulator
    const int n4 = N * 16;
    zero_kernel<<<(n4 + 255) / 256, 256>>>((float4*)agg, n4);

    // Per-edge gather/gate/scatter (one warp per edge)
    edge_kernel<<<(E + 7) / 8, 256>>>(edges, hidden, rela, wa_W, wa_b,
                                      tS, tR, tQ, tQR, agg, alpha_out, E, R);

    // Final projection: hidden_new = agg @ Wh^T
    gemm_nt_kernel<<<(N + 31) / 32, 256>>>(agg, Wh_W, nullptr, out, N);
}

// round 2
// speedup vs baseline: 1.9144x; 1.9144x over previous
#include <cuda_runtime.h>
#include <math.h>

// Fixed problem shape
#define NMAX 100000
#define QMAX 256
#define RMAX 401
#define BM   128

// Scratch (device globals — no allocation allowed)
__device__ float g_tableS[NMAX * 64];           // Ws·hidden + Ws_b          (25.6 MB)
__device__ float g_tableR[RMAX * 64];           // Wr·rela
__device__ float g_tableQ[QMAX * 64];           // Wq·q_emb
__device__ float g_tableQR[QMAX * RMAX * 64];   // Wqr·(rela⊙q) + tR + tQ    (26.3 MB)
__device__ float g_agg[NMAX * 64];              // segment-sum accumulator   (25.6 MB)

__device__ __forceinline__ void mac4(float4& a, const float4 x,
                                     const float4 w0, const float4 w1,
                                     const float4 w2, const float4 w3)
{
    a.x = fmaf(x.x, w0.x, fmaf(x.y, w1.x, fmaf(x.z, w2.x, fmaf(x.w, w3.x, a.x))));
    a.y = fmaf(x.x, w0.y, fmaf(x.y, w1.y, fmaf(x.z, w2.y, fmaf(x.w, w3.y, a.y))));
    a.z = fmaf(x.x, w0.z, fmaf(x.y, w1.z, fmaf(x.z, w2.z, fmaf(x.w, w3.z, a.z))));
    a.w = fmaf(x.x, w0.w, fmaf(x.y, w1.w, fmaf(x.z, w2.w, fmaf(x.w, w3.w, a.w))));
}

// -----------------------------------------------------------------------------
// GEMM (NT): out[m,a] = sum_d X[m,d] * W[a,d] (+ bias[a]).  D = A = 64.
// Block tile BM=128 rows x 64 cols, 256 threads, each does 8 rows x 4 cols.
// 12 LDS.128 per 128 FMA -> FMA-bound (was 6 per 32 -> L1-bound).
// -----------------------------------------------------------------------------
__global__ __launch_bounds__(256)
void gemm_nt_kernel(const float* __restrict__ X,
                    const float* __restrict__ W,
                    const float* __restrict__ bias,
                    float* __restrict__ out, int M)
{
    __shared__ float Wt[64 * 64];     // Wt[d*64 + a] = W[a*64 + d]
    __shared__ float Xs[BM * 64];
    const int tid = threadIdx.x;

    #pragma unroll
    for (int i = tid; i < 4096; i += 256)
        Wt[i] = W[((i & 63) << 6) | (i >> 6)];

    const int m0 = blockIdx.x * BM;
    #pragma unroll
    for (int i = tid; i < BM * 16; i += 256) {
        int row = i >> 4;
        float4 v = make_float4(0.f, 0.f, 0.f, 0.f);
        if (m0 + row < M) v = __ldg(&((const float4*)X)[(size_t)(m0 + row) * 16 + (i & 15)]);
        ((float4*)Xs)[i] = v;
    }
    __syncthreads();

    const int a0 = (tid & 15) * 4;
    const int r0 = (tid >> 4) * 8;

    float4 binit = make_float4(0.f, 0.f, 0.f, 0.f);
    if (bias) binit = *(const float4*)&bias[a0];
    float4 acc[8];
    #pragma unroll
    for (int i = 0; i < 8; i++) acc[i] = binit;

    #pragma unroll
    for (int d = 0; d < 64; d += 4) {
        float4 w0 = *(const float4*)&Wt[(d + 0) * 64 + a0];
        float4 w1 = *(const float4*)&Wt[(d + 1) * 64 + a0];
        float4 w2 = *(const float4*)&Wt[(d + 2) * 64 + a0];
        float4 w3 = *(const float4*)&Wt[(d + 3) * 64 + a0];
        #pragma unroll
        for (int i = 0; i < 8; i++) {
            float4 xv = *(const float4*)&Xs[(r0 + i) * 64 + d];
            mac4(acc[i], xv, w0, w1, w2, w3);
        }
    }

    #pragma unroll
    for (int i = 0; i < 8; i++)
        if (m0 + r0 + i < M)
            *(float4*)&out[(size_t)(m0 + r0 + i) * 64 + a0] = acc[i];
}

// -----------------------------------------------------------------------------
// QR GEMM: row p=(q,r): X = q_emb[q] ⊙ rela[r]; out = X·Wqr^T + tR[r] + tQ[q]
// (folds the rel and query tables in, so the edge kernel gathers 2 tables).
// -----------------------------------------------------------------------------
__global__ __launch_bounds__(256)
void gemm_qr_kernel(const float* __restrict__ qe,
                    const float* __restrict__ re,
                    const float* __restrict__ W,
                    const float* __restrict__ tR,
                    const float* __restrict__ tQ,
                    float* __restrict__ out, int M, int R)
{
    __shared__ float Wt[64 * 64];
    __shared__ float Xs[BM * 64];
    const int tid = threadIdx.x;

    #pragma unroll
    for (int i = tid; i < 4096; i += 256)
        Wt[i] = W[((i & 63) << 6) | (i >> 6)];

    const int m0 = blockIdx.x * BM;
    #pragma unroll
    for (int i = tid; i < BM * 16; i += 256) {
        int row = i >> 4, c4 = i & 15;
        float4 v = make_float4(0.f, 0.f, 0.f, 0.f);
        int p = m0 + row;
        if (p < M) {
            int q = p / R;
            int r = p - q * R;
            float4 a = __ldg(&((const float4*)qe)[q * 16 + c4]);
            float4 b = __ldg(&((const float4*)re)[r * 16 + c4]);
            v = make_float4(a.x * b.x, a.y * b.y, a.z * b.z, a.w * b.w);
        }
        ((float4*)Xs)[i] = v;
    }
    __syncthreads();

    const int a0 = (tid & 15) * 4;
    const int r0 = (tid >> 4) * 8;
    float4 acc[8];
    #pragma unroll
    for (int i = 0; i < 8; i++) acc[i] = make_float4(0.f, 0.f, 0.f, 0.f);

    #pragma unroll
    for (int d = 0; d < 64; d += 4) {
        float4 w0 = *(const float4*)&Wt[(d + 0) * 64 + a0];
        float4 w1 = *(const float4*)&Wt[(d + 1) * 64 + a0];
        float4 w2 = *(const float4*)&Wt[(d + 2) * 64 + a0];
        float4 w3 = *(const float4*)&Wt[(d + 3) * 64 + a0];
        #pragma unroll
        for (int i = 0; i < 8; i++) {
            float4 xv = *(const float4*)&Xs[(r0 + i) * 64 + d];
            mac4(acc[i], xv, w0, w1, w2, w3);
        }
    }

    const int ac = a0 >> 2;
    #pragma unroll
    for (int i = 0; i < 8; i++) {
        int p = m0 + r0 + i;
        if (p < M) {
            int q = p / R;
            int r = p - q * R;
            float4 t1 = __ldg(&((const float4*)tR)[r * 16 + ac]);
            float4 t2 = __ldg(&((const float4*)tQ)[q * 16 + ac]);
            float4 v = acc[i];
            v.x += t1.x + t2.x; v.y += t1.y + t2.y;
            v.z += t1.z + t2.z; v.w += t1.w + t2.w;
            *(float4*)&out[(size_t)p * 64 + a0] = v;
        }
    }
}

// -----------------------------------------------------------------------------
__global__ void zero_kernel(float4* __restrict__ p, int n4)
{
    int i = blockIdx.x * blockDim.x + threadIdx.x;
    if (i < n4) p[i] = make_float4(0.f, 0.f, 0.f, 0.f);
}

// -----------------------------------------------------------------------------
// Edge kernel: half-warp (16 lanes) per edge, float4 per lane.
// pre = tS[s] + tQR'[q,r]; gate = sigmoid(wa·relu(pre)+b);
// message = gate * hidden[s] ⊙ rela[r]; red.v4 scatter into agg[obj].
// -----------------------------------------------------------------------------
__global__ __launch_bounds__(256)
void edge_kernel(const int* __restrict__ edges,
                 const float* __restrict__ hidden,
                 const float* __restrict__ rela,
                 const float* __restrict__ wa_W,
                 const float* __restrict__ wa_b,
                 const float* __restrict__ tS,
                 const float* __restrict__ tQR,
                 float* __restrict__ agg,
                 float* __restrict__ alpha_out,
                 int E, int R)
{
    const int t = blockIdx.x * 256 + threadIdx.x;
    const int e = t >> 4;
    if (e >= E) return;
    const int sl = t & 15;

    const int* er = edges + (size_t)e * 6;
    const int q = __ldg(er + 0);
    const int r = __ldg(er + 2);
    const int s = __ldg(er + 4);
    const int o = __ldg(er + 5);

    float4 g   = __ldg(&((const float4*)tS)[(size_t)s * 16 + sl]);
    float4 p2  = __ldg(&((const float4*)tQR)[((size_t)q * R + r) * 16 + sl]);
    float4 hs  = __ldg(&((const float4*)hidden)[(size_t)s * 16 + sl]);
    float4 hr  = __ldg(&((const float4*)rela)[(size_t)r * 16 + sl]);
    float4 wa  = __ldg(&((const float4*)wa_W)[sl]);

    float px = fmaxf(g.x + p2.x, 0.f);
    float py = fmaxf(g.y + p2.y, 0.f);
    float pz = fmaxf(g.z + p2.z, 0.f);
    float pw = fmaxf(g.w + p2.w, 0.f);

    float part = fmaf(px, wa.x, fmaf(py, wa.y, fmaf(pz, wa.z, pw * wa.w)));
    #pragma unroll
    for (int off = 8; off; off >>= 1)
        part += __shfl_xor_sync(0xffffffffu, part, off);

    float alpha = 1.0f / (1.0f + __expf(-(part + __ldg(wa_b))));
    if (sl == 0) alpha_out[e] = alpha;

    float4 m;
    m.x = alpha * hs.x * hr.x;
    m.y = alpha * hs.y * hr.y;
    m.z = alpha * hs.z * hr.z;
    m.w = alpha * hs.w * hr.w;

    float* dst = &agg[(size_t)o * 64 + sl * 4];
    asm volatile("red.global.add.v4.f32 [%0], {%1, %2, %3, %4};"
                 :: "l"(dst), "f"(m.x), "f"(m.y), "f"(m.z), "f"(m.w) : "memory");
}

// -----------------------------------------------------------------------------
extern "C" void kernel_launch(void* const* d_in, const int* in_sizes, int n_in,
                              void* d_out, int out_size)
{
    const float* q_emb  = (const float*)d_in[1];
    const float* rela   = (const float*)d_in[2];
    const float* hidden = (const float*)d_in[3];
    const int*   edges  = (const int*)d_in[4];
    const float* Ws_W   = (const float*)d_in[6];
    const float* Ws_b   = (const float*)d_in[7];
    const float* Wr_W   = (const float*)d_in[8];
    const float* Wq_W   = (const float*)d_in[9];
    const float* Wqr_W  = (const float*)d_in[10];
    const float* wa_W   = (const float*)d_in[11];
    const float* wa_b   = (const float*)d_in[12];
    const float* Wh_W   = (const float*)d_in[13];

    const int Q = in_sizes[0];
    const int R = in_sizes[2] / 64;
    const int N = in_sizes[3] / 64;
    const int E = in_sizes[4] / 6;

    float* out = (float*)d_out;
    float* alpha_out = out + (size_t)N * 64;

    float *tS, *tR, *tQ, *tQR, *agg;
    cudaGetSymbolAddress((void**)&tS,  g_tableS);
    cudaGetSymbolAddress((void**)&tR,  g_tableR);
    cudaGetSymbolAddress((void**)&tQ,  g_tableQ);
    cudaGetSymbolAddress((void**)&tQR, g_tableQR);
    cudaGetSymbolAddress((void**)&agg, g_agg);

    // Small tables first (inputs to the QR fold)
    gemm_nt_kernel<<<(R + BM - 1) / BM, 256>>>(rela,  Wr_W, nullptr, tR, R);
    gemm_nt_kernel<<<(Q + BM - 1) / BM, 256>>>(q_emb, Wq_W, nullptr, tQ, Q);

    // Big precomputes
    gemm_nt_kernel<<<(N + BM - 1) / BM, 256>>>(hidden, Ws_W, Ws_b, tS, N);
    gemm_qr_kernel<<<(Q * R + BM - 1) / BM, 256>>>(q_emb, rela, Wqr_W, tR, tQ,
                                                   tQR, Q * R, R);

    // Zero accumulator
    const int n4 = N * 16;
    zero_kernel<<<(n4 + 255) / 256, 256>>>((float4*)agg, n4);

    // Per-edge gather/gate/scatter (half-warp per edge)
    edge_kernel<<<(E * 16 + 255) / 256, 256>>>(edges, hidden, rela, wa_W, wa_b,
                                               tS, tQR, agg, alpha_out, E, R);

    // Final projection: hidden_new = agg @ Wh^T
    gemm_nt_kernel<<<(N + BM - 1) / BM, 256>>>(agg, Wh_W, nullptr, out, N);
}